// round 3
// baseline (speedup 1.0000x reference)
#include <cuda_runtime.h>
#include <cuda_bf16.h>

// Problem constants
#define SEQ_LEN 512
#define EMBED_DIM 768
#define MAX_SPAN_LEN 16
#define WIDTH_EMB 50
#define NUM_LABELS 9
#define N_SPANS 32768
#define W_COLS (3 * EMBED_DIM + WIDTH_EMB)   // 2354

// Padded row stride so each 9-float table row is 48B (16B aligned) -> float4 loads
#define PSTRIDE 12

// Scratch tables (device globals; no allocation allowed)
__device__ float g_ps[SEQ_LEN * PSTRIDE];        // W[:,0:768]    . seq[t]
__device__ float g_pe[SEQ_LEN * PSTRIDE];        // W[:,768:1536] . seq[t]
__device__ float g_pa[SEQ_LEN * PSTRIDE];        // W[:,1536:2304]. seq[t]   (pre-scan)
__device__ float g_pacs[(SEQ_LEN + 8) * PSTRIDE];// exclusive scan of g_pa over t (513 rows used)
__device__ float g_pw[(MAX_SPAN_LEN + 1) * PSTRIDE]; // W[:,2304:] . width_table[w] + b
__device__ float g_invw[MAX_SPAN_LEN + 1];

// ---------------------------------------------------------------------------
// Kernel A: per-token projections, thread-per-(token, output).
// Block = 4 tokens x 27 outputs = 108 threads; grid = 128 blocks.
// Each thread owns one scalar dot product of length 768:
//   - seq row staged in smem (shared by 27 threads of the same token)
//   - W segment streamed contiguously (float2; rows are 8B-aligned only)
//   - 4 independent accumulators to break the FMA RAW chain
//   - no reduction: scalar result written straight to the table
// ---------------------------------------------------------------------------
#define TOK_PER_BLK 4
#define PROJ_THREADS (TOK_PER_BLK * 27)

__global__ __launch_bounds__(PROJ_THREADS) void proj_kernel(const float* __restrict__ seq,
                                                            const float* __restrict__ W) {
    __shared__ float srow[TOK_PER_BLK][EMBED_DIM];
    const int t0 = blockIdx.x * TOK_PER_BLK;

    // cooperative float4 load of 4 seq rows (3072 floats)
    const float4* src = (const float4*)(seq + (size_t)t0 * EMBED_DIM);
    float4* dst = (float4*)&srow[0][0];
    #pragma unroll
    for (int i = threadIdx.x; i < TOK_PER_BLK * EMBED_DIM / 4; i += PROJ_THREADS)
        dst[i] = src[i];
    __syncthreads();

    const int tok = threadIdx.x / 27;          // 0..3
    const int o   = threadIdx.x - tok * 27;    // 0..26
    const int k   = o / 9;                     // which W block (start/end/avg)
    const int l   = o - k * 9;                 // label

    const float2* w2 = (const float2*)(W + (size_t)l * W_COLS + k * EMBED_DIM);
    const float2* s2 = (const float2*)srow[tok];

    float a0 = 0.f, a1 = 0.f, a2 = 0.f, a3 = 0.f;
    #pragma unroll 4
    for (int j = 0; j < EMBED_DIM / 2; j += 2) {
        const float2 sa = s2[j];
        const float2 wa = __ldg(&w2[j]);
        const float2 sb = s2[j + 1];
        const float2 wb = __ldg(&w2[j + 1]);
        a0 = fmaf(sa.x, wa.x, a0);
        a1 = fmaf(sa.y, wa.y, a1);
        a2 = fmaf(sb.x, wb.x, a2);
        a3 = fmaf(sb.y, wb.y, a3);
    }
    const float r = (a0 + a1) + (a2 + a3);

    float* tbl = (k == 0) ? g_ps : (k == 1) ? g_pe : g_pa;
    tbl[(t0 + tok) * PSTRIDE + l] = r;
}

// ---------------------------------------------------------------------------
// Kernel B: single block. (1) width-projection LUT + bias, (2) 1/w LUT,
// (3) exclusive prefix-scan of g_pa over tokens: warp-per-label.
// ---------------------------------------------------------------------------
__global__ __launch_bounds__(288) void scan_kernel(const float* __restrict__ width_table,
                                                   const float* __restrict__ W,
                                                   const float* __restrict__ b) {
    const int tid = threadIdx.x;

    // pw[w][l] = b[l] + width_table[w] . W[l, 2304:2354]
    if (tid < (MAX_SPAN_LEN + 1) * NUM_LABELS) {
        const int w = tid / NUM_LABELS;
        const int l = tid - w * NUM_LABELS;
        const float* wrow = W + (size_t)l * W_COLS + 3 * EMBED_DIM;
        const float* wt = width_table + w * WIDTH_EMB;
        float acc = b[l];
        #pragma unroll
        for (int j = 0; j < WIDTH_EMB; j++)
            acc = fmaf(wt[j], wrow[j], acc);
        g_pw[w * PSTRIDE + l] = acc;
    }
    if (tid <= MAX_SPAN_LEN)
        g_invw[tid] = 1.0f / (float)(tid < 1 ? 1 : tid);

    // exclusive scan over t=0..512 for each label column (9 warps)
    const int warp = tid >> 5;
    const int lane = tid & 31;
    if (warp < NUM_LABELS) {
        const int l = warp;
        float carry = 0.f;
        #pragma unroll 1
        for (int c = 0; c < 17; c++) {
            const int t = c * 32 + lane;
            const float v = (t < SEQ_LEN) ? g_pa[t * PSTRIDE + l] : 0.f;
            float x = v;
            #pragma unroll
            for (int off = 1; off < 32; off <<= 1) {
                float y = __shfl_up_sync(0xffffffffu, x, off);
                if (lane >= off) x += y;
            }
            const float excl = carry + x - v;
            if (t <= SEQ_LEN)
                g_pacs[t * PSTRIDE + l] = excl;
            carry += __shfl_sync(0xffffffffu, x, 31);
        }
    }
}

// ---------------------------------------------------------------------------
// Kernel C: one thread per span; all table rows are 3x float4; output staged
// through smem for coalesced float4 stores.
// ---------------------------------------------------------------------------
#define SPAN_BLK 256
__global__ __launch_bounds__(SPAN_BLK) void span_kernel(const int* __restrict__ sidx,
                                                        const int* __restrict__ eidx,
                                                        const int* __restrict__ widx,
                                                        float* __restrict__ out) {
    __shared__ float so[SPAN_BLK * NUM_LABELS];
    const int n = blockIdx.x * SPAN_BLK + threadIdx.x;

    const int s = sidx[n];
    const int e = eidx[n];
    const int w = widx[n];
    const float invw = g_invw[w];

    const float4* ps = (const float4*)(g_ps + s * PSTRIDE);
    const float4* pe = (const float4*)(g_pe + e * PSTRIDE);
    const float4* c0 = (const float4*)(g_pacs + s * PSTRIDE);
    const float4* c1 = (const float4*)(g_pacs + e * PSTRIDE);
    const float4* pw = (const float4*)(g_pw + w * PSTRIDE);

    float r[12];
    #pragma unroll
    for (int q = 0; q < 3; q++) {
        const float4 a = ps[q], bb = pe[q], x0 = c0[q], x1 = c1[q], d = pw[q];
        r[q * 4 + 0] = a.x + bb.x + (x1.x - x0.x) * invw + d.x;
        r[q * 4 + 1] = a.y + bb.y + (x1.y - x0.y) * invw + d.y;
        r[q * 4 + 2] = a.z + bb.z + (x1.z - x0.z) * invw + d.z;
        r[q * 4 + 3] = a.w + bb.w + (x1.w - x0.w) * invw + d.w;
    }

    #pragma unroll
    for (int l = 0; l < NUM_LABELS; l++)
        so[threadIdx.x * NUM_LABELS + l] = r[l];
    __syncthreads();

    float4* ob = (float4*)(out + (size_t)blockIdx.x * SPAN_BLK * NUM_LABELS);
    const float4* sb = (const float4*)so;
    #pragma unroll
    for (int i = threadIdx.x; i < SPAN_BLK * NUM_LABELS / 4; i += SPAN_BLK)
        ob[i] = sb[i];
}

// ---------------------------------------------------------------------------
// Launcher
// ---------------------------------------------------------------------------
extern "C" void kernel_launch(void* const* d_in, const int* in_sizes, int n_in,
                              void* d_out, int out_size) {
    const float* seq   = (const float*)d_in[0];   // [1, 512, 768]
    const int*   sidx  = (const int*)d_in[1];     // [32768]
    const int*   eidx  = (const int*)d_in[2];     // [32768]
    const int*   widx  = (const int*)d_in[3];     // [32768]
    const float* wtab  = (const float*)d_in[4];   // [17, 50]
    const float* W     = (const float*)d_in[5];   // [9, 2354]
    const float* b     = (const float*)d_in[6];   // [9]
    float* out = (float*)d_out;                   // [32768, 9]

    proj_kernel<<<SEQ_LEN / TOK_PER_BLK, PROJ_THREADS>>>(seq, W);
    scan_kernel<<<1, 288>>>(wtab, W, b);
    span_kernel<<<N_SPANS / SPAN_BLK, SPAN_BLK>>>(sidx, eidx, widx, out);
}

// round 5
// speedup vs baseline: 1.2294x; 1.2294x over previous
#include <cuda_runtime.h>
#include <cuda_bf16.h>

// Problem constants
#define SEQ_LEN 512
#define EMBED_DIM 768
#define MAX_SPAN_LEN 16
#define WIDTH_EMB 50
#define NUM_LABELS 9
#define N_SPANS 32768
#define W_COLS (3 * EMBED_DIM + WIDTH_EMB)   // 2354

// Padded row stride so each 9-float table row is 48B (16B aligned) -> float4 loads
#define PSTRIDE 12

// Scratch tables (device globals; no allocation allowed)
__device__ float g_ps[SEQ_LEN * PSTRIDE];        // W[:,0:768]    . seq[t]
__device__ float g_pe[SEQ_LEN * PSTRIDE];        // W[:,768:1536] . seq[t]
__device__ float g_pa[SEQ_LEN * PSTRIDE];        // W[:,1536:2304]. seq[t]   (pre-scan)
__device__ float g_pacs[(SEQ_LEN + 8) * PSTRIDE];// exclusive scan of g_pa over t (513 rows used)
__device__ float g_pw[(MAX_SPAN_LEN + 1) * PSTRIDE]; // W[:,2304:] . width_table[w] + b
__device__ float g_invw[MAX_SPAN_LEN + 1];

// ---------------------------------------------------------------------------
// Kernel A: per-token projections. Warp-per-token, lane-over-k.
//   - every load is warp-coalesced (lanes read consecutive float2 of ONE row)
//   - 27 independent accumulators per lane -> deep ILP, no RAW chain
//   - W rows are only 8B-aligned (2354 odd*2), so float2 is the widest legal
//   - epilogue: 27 shuffle reductions, lane 0 scatters to the tables
// ---------------------------------------------------------------------------
#define PROJ_TPB 128   // 4 warps = 4 tokens per block
#define PROJ_GRID (SEQ_LEN / 4)

__global__ __launch_bounds__(PROJ_TPB) void proj_kernel(const float* __restrict__ seq,
                                                        const float* __restrict__ W) {
    const int warp = threadIdx.x >> 5;
    const int lane = threadIdx.x & 31;
    const int t = blockIdx.x * 4 + warp;

    const float2* __restrict__ s2 = (const float2*)(seq + (size_t)t * EMBED_DIM);
    const float2* __restrict__ w2 = (const float2*)W;   // W_COLS even -> rows 8B aligned

    float acc[27];
    #pragma unroll
    for (int o = 0; o < 27; o++) acc[o] = 0.f;

    #pragma unroll 2
    for (int kk = 0; kk < EMBED_DIM / 2 / 32; kk++) {   // 12 iterations
        const int k2 = kk * 32 + lane;                   // float2 index within the 768 block
        const float2 s = s2[k2];
        #pragma unroll
        for (int o = 0; o < 27; o++) {
            const int kblk = o / 9;                      // which 768-block of W
            const int l    = o - kblk * 9;               // label row
            // float2 offset: (l*W_COLS + kblk*EMBED_DIM)/2 + k2 (compile-time consts)
            const float2 wv = __ldg(w2 + (l * (W_COLS / 2) + kblk * (EMBED_DIM / 2)) + k2);
            acc[o] = fmaf(s.x, wv.x, fmaf(s.y, wv.y, acc[o]));
        }
    }

    // warp reductions + scatter (lane 0)
    #pragma unroll
    for (int o = 0; o < 27; o++) {
        float v = acc[o];
        #pragma unroll
        for (int off = 16; off; off >>= 1)
            v += __shfl_down_sync(0xffffffffu, v, off);
        if (lane == 0) {
            const int kblk = o / 9;
            const int l    = o - kblk * 9;
            float* tbl = (kblk == 0) ? g_ps : (kblk == 1) ? g_pe : g_pa;
            tbl[t * PSTRIDE + l] = v;
        }
    }
}

// ---------------------------------------------------------------------------
// Kernel B: single block. (1) width-projection LUT + bias, (2) 1/w LUT,
// (3) exclusive prefix-scan of g_pa over tokens: warp-per-label.
// ---------------------------------------------------------------------------
__global__ __launch_bounds__(288) void scan_kernel(const float* __restrict__ width_table,
                                                   const float* __restrict__ W,
                                                   const float* __restrict__ b) {
    const int tid = threadIdx.x;

    // pw[w][l] = b[l] + width_table[w] . W[l, 2304:2354]
    if (tid < (MAX_SPAN_LEN + 1) * NUM_LABELS) {
        const int w = tid / NUM_LABELS;
        const int l = tid - w * NUM_LABELS;
        const float* wrow = W + (size_t)l * W_COLS + 3 * EMBED_DIM;
        const float* wt = width_table + w * WIDTH_EMB;
        float acc = b[l];
        #pragma unroll
        for (int j = 0; j < WIDTH_EMB; j++)
            acc = fmaf(wt[j], wrow[j], acc);
        g_pw[w * PSTRIDE + l] = acc;
    }
    if (tid <= MAX_SPAN_LEN)
        g_invw[tid] = 1.0f / (float)(tid < 1 ? 1 : tid);

    // exclusive scan over t=0..512 for each label column (9 warps)
    const int warp = tid >> 5;
    const int lane = tid & 31;
    if (warp < NUM_LABELS) {
        const int l = warp;
        float carry = 0.f;
        #pragma unroll 1
        for (int c = 0; c < 17; c++) {
            const int t = c * 32 + lane;
            const float v = (t < SEQ_LEN) ? g_pa[t * PSTRIDE + l] : 0.f;
            float x = v;
            #pragma unroll
            for (int off = 1; off < 32; off <<= 1) {
                float y = __shfl_up_sync(0xffffffffu, x, off);
                if (lane >= off) x += y;
            }
            const float excl = carry + x - v;
            if (t <= SEQ_LEN)
                g_pacs[t * PSTRIDE + l] = excl;
            carry += __shfl_sync(0xffffffffu, x, 31);
        }
    }
}

// ---------------------------------------------------------------------------
// Kernel C: one thread per span; all table rows are 3x float4; output staged
// through smem for coalesced float4 stores.
// ---------------------------------------------------------------------------
#define SPAN_BLK 256
__global__ __launch_bounds__(SPAN_BLK) void span_kernel(const int* __restrict__ sidx,
                                                        const int* __restrict__ eidx,
                                                        const int* __restrict__ widx,
                                                        float* __restrict__ out) {
    __shared__ float so[SPAN_BLK * NUM_LABELS];
    const int n = blockIdx.x * SPAN_BLK + threadIdx.x;

    const int s = sidx[n];
    const int e = eidx[n];
    const int w = widx[n];
    const float invw = g_invw[w];

    const float4* ps = (const float4*)(g_ps + s * PSTRIDE);
    const float4* pe = (const float4*)(g_pe + e * PSTRIDE);
    const float4* c0 = (const float4*)(g_pacs + s * PSTRIDE);
    const float4* c1 = (const float4*)(g_pacs + e * PSTRIDE);
    const float4* pw = (const float4*)(g_pw + w * PSTRIDE);

    float r[12];
    #pragma unroll
    for (int q = 0; q < 3; q++) {
        const float4 a = ps[q], bb = pe[q], x0 = c0[q], x1 = c1[q], d = pw[q];
        r[q * 4 + 0] = a.x + bb.x + (x1.x - x0.x) * invw + d.x;
        r[q * 4 + 1] = a.y + bb.y + (x1.y - x0.y) * invw + d.y;
        r[q * 4 + 2] = a.z + bb.z + (x1.z - x0.z) * invw + d.z;
        r[q * 4 + 3] = a.w + bb.w + (x1.w - x0.w) * invw + d.w;
    }

    #pragma unroll
    for (int l = 0; l < NUM_LABELS; l++)
        so[threadIdx.x * NUM_LABELS + l] = r[l];
    __syncthreads();

    float4* ob = (float4*)(out + (size_t)blockIdx.x * SPAN_BLK * NUM_LABELS);
    const float4* sb = (const float4*)so;
    #pragma unroll
    for (int i = threadIdx.x; i < SPAN_BLK * NUM_LABELS / 4; i += SPAN_BLK)
        ob[i] = sb[i];
}

// ---------------------------------------------------------------------------
// Launcher
// ---------------------------------------------------------------------------
extern "C" void kernel_launch(void* const* d_in, const int* in_sizes, int n_in,
                              void* d_out, int out_size) {
    const float* seq   = (const float*)d_in[0];   // [1, 512, 768]
    const int*   sidx  = (const int*)d_in[1];     // [32768]
    const int*   eidx  = (const int*)d_in[2];     // [32768]
    const int*   widx  = (const int*)d_in[3];     // [32768]
    const float* wtab  = (const float*)d_in[4];   // [17, 50]
    const float* W     = (const float*)d_in[5];   // [9, 2354]
    const float* b     = (const float*)d_in[6];   // [9]
    float* out = (float*)d_out;                   // [32768, 9]

    proj_kernel<<<PROJ_GRID, PROJ_TPB>>>(seq, W);
    scan_kernel<<<1, 288>>>(wtab, W, b);
    span_kernel<<<N_SPANS / SPAN_BLK, SPAN_BLK>>>(sidx, eidx, widx, out);
}

// round 7
// speedup vs baseline: 1.8951x; 1.5415x over previous
#include <cuda_runtime.h>
#include <cuda_bf16.h>

// Problem constants
#define SEQ_LEN 512
#define EMBED_DIM 768
#define MAX_SPAN_LEN 16
#define WIDTH_EMB 50
#define NUM_LABELS 9
#define N_SPANS 32768
#define W_COLS (3 * EMBED_DIM + WIDTH_EMB)   // 2354

// Padded row stride so each 9-float table row is 48B (16B aligned) -> float4 loads
#define PSTRIDE 12

// Scratch tables (device globals; no allocation allowed)
__device__ float g_ps[SEQ_LEN * PSTRIDE];        // W[:,0:768]    . seq[t]
__device__ float g_pe[SEQ_LEN * PSTRIDE];        // W[:,768:1536] . seq[t]
__device__ float g_pa[SEQ_LEN * PSTRIDE];        // W[:,1536:2304]. seq[t]   (pre-scan)
__device__ float g_pacs[(SEQ_LEN + 8) * PSTRIDE];// exclusive scan of g_pa over t (513 rows used)
__device__ float g_pw[(MAX_SPAN_LEN + 1) * PSTRIDE]; // W[:,2304:] . width_table[w] + b
__device__ float g_invw[MAX_SPAN_LEN + 1];

// ---------------------------------------------------------------------------
// Kernel A: per-token projections. Warp-per-token, W staged through smem in
// two k-chunks so the inner loop is pure LDS+FMA (no L2 latency exposed).
//   - ws fill: float2, coalesced, MLP~40 -> L2 latency overlapped
//   - seq chunk prefetched into 6 regs (independent LDG.64) before inner loop
//   - inner: 27 independent accumulators; LDS.64 conflict-free
// ---------------------------------------------------------------------------
#define PROJ_TPB 128                 // 4 warps = 4 tokens per block
#define PROJ_GRID (SEQ_LEN / 4)      // 128 blocks
#define CHUNK 384                    // k-elements per chunk
#define CHUNK2 (CHUNK / 2)           // float2 per chunk = 192
#define NCHUNK (EMBED_DIM / CHUNK)   // 2

__global__ __launch_bounds__(PROJ_TPB) void proj_kernel(const float* __restrict__ seq,
                                                        const float* __restrict__ W) {
    __shared__ float2 ws[27 * CHUNK2];           // 40.5 KB

    const int warp = threadIdx.x >> 5;
    const int lane = threadIdx.x & 31;
    const int t = blockIdx.x * 4 + warp;

    const float2* __restrict__ s2 = (const float2*)(seq + (size_t)t * EMBED_DIM);
    const float2* __restrict__ w2 = (const float2*)W;   // W_COLS even -> rows 8B aligned

    float acc[27];
    #pragma unroll
    for (int o = 0; o < 27; o++) acc[o] = 0.f;

    #pragma unroll
    for (int c = 0; c < NCHUNK; c++) {
        if (c) __syncthreads();      // protect previous chunk's reads
        // cooperative fill of ws for this chunk: 27 rows x 192 float2
        #pragma unroll
        for (int i = threadIdx.x; i < 27 * CHUNK2; i += PROJ_TPB) {
            const int o  = i / CHUNK2;
            const int j2 = i - o * CHUNK2;
            const int kblk = o / 9;
            const int l    = o - kblk * 9;
            ws[i] = __ldg(w2 + (size_t)l * (W_COLS / 2) + kblk * (EMBED_DIM / 2)
                             + c * CHUNK2 + j2);
        }
        // prefetch this warp's seq chunk: 6 independent coalesced LDG.64
        float2 sv[6];
        #pragma unroll
        for (int kk = 0; kk < 6; kk++)
            sv[kk] = s2[c * CHUNK2 + kk * 32 + lane];
        __syncthreads();

        #pragma unroll
        for (int kk = 0; kk < 6; kk++) {
            const float2 s = sv[kk];
            #pragma unroll
            for (int o = 0; o < 27; o++) {
                const float2 wv = ws[o * CHUNK2 + kk * 32 + lane];
                acc[o] = fmaf(s.x, wv.x, fmaf(s.y, wv.y, acc[o]));
            }
        }
    }

    // warp reductions + scatter (lane 0)
    #pragma unroll
    for (int o = 0; o < 27; o++) {
        float v = acc[o];
        #pragma unroll
        for (int off = 16; off; off >>= 1)
            v += __shfl_down_sync(0xffffffffu, v, off);
        if (lane == 0) {
            const int kblk = o / 9;
            const int l    = o - kblk * 9;
            float* tbl = (kblk == 0) ? g_ps : (kblk == 1) ? g_pe : g_pa;
            tbl[t * PSTRIDE + l] = v;
        }
    }
}

// ---------------------------------------------------------------------------
// Kernel B: single block. (1) width-projection LUT + bias, (2) 1/w LUT,
// (3) exclusive prefix-scan of g_pa over tokens: warp-per-label.
// ---------------------------------------------------------------------------
__global__ __launch_bounds__(288) void scan_kernel(const float* __restrict__ width_table,
                                                   const float* __restrict__ W,
                                                   const float* __restrict__ b) {
    const int tid = threadIdx.x;

    // pw[w][l] = b[l] + width_table[w] . W[l, 2304:2354]
    if (tid < (MAX_SPAN_LEN + 1) * NUM_LABELS) {
        const int w = tid / NUM_LABELS;
        const int l = tid - w * NUM_LABELS;
        const float* wrow = W + (size_t)l * W_COLS + 3 * EMBED_DIM;
        const float* wt = width_table + w * WIDTH_EMB;
        float acc = b[l];
        #pragma unroll
        for (int j = 0; j < WIDTH_EMB; j++)
            acc = fmaf(wt[j], wrow[j], acc);
        g_pw[w * PSTRIDE + l] = acc;
    }
    if (tid <= MAX_SPAN_LEN)
        g_invw[tid] = 1.0f / (float)(tid < 1 ? 1 : tid);

    // exclusive scan over t=0..512 for each label column (9 warps)
    const int warp = tid >> 5;
    const int lane = tid & 31;
    if (warp < NUM_LABELS) {
        const int l = warp;
        float carry = 0.f;
        #pragma unroll 1
        for (int c = 0; c < 17; c++) {
            const int t = c * 32 + lane;
            const float v = (t < SEQ_LEN) ? g_pa[t * PSTRIDE + l] : 0.f;
            float x = v;
            #pragma unroll
            for (int off = 1; off < 32; off <<= 1) {
                float y = __shfl_up_sync(0xffffffffu, x, off);
                if (lane >= off) x += y;
            }
            const float excl = carry + x - v;
            if (t <= SEQ_LEN)
                g_pacs[t * PSTRIDE + l] = excl;
            carry += __shfl_sync(0xffffffffu, x, 31);
        }
    }
}

// ---------------------------------------------------------------------------
// Kernel C: one thread per span; all table rows are 3x float4; output staged
// through smem for coalesced float4 stores.
// ---------------------------------------------------------------------------
#define SPAN_BLK 256
__global__ __launch_bounds__(SPAN_BLK) void span_kernel(const int* __restrict__ sidx,
                                                        const int* __restrict__ eidx,
                                                        const int* __restrict__ widx,
                                                        float* __restrict__ out) {
    __shared__ float so[SPAN_BLK * NUM_LABELS];
    const int n = blockIdx.x * SPAN_BLK + threadIdx.x;

    const int s = sidx[n];
    const int e = eidx[n];
    const int w = widx[n];
    const float invw = g_invw[w];

    const float4* ps = (const float4*)(g_ps + s * PSTRIDE);
    const float4* pe = (const float4*)(g_pe + e * PSTRIDE);
    const float4* c0 = (const float4*)(g_pacs + s * PSTRIDE);
    const float4* c1 = (const float4*)(g_pacs + e * PSTRIDE);
    const float4* pw = (const float4*)(g_pw + w * PSTRIDE);

    float r[12];
    #pragma unroll
    for (int q = 0; q < 3; q++) {
        const float4 a = ps[q], bb = pe[q], x0 = c0[q], x1 = c1[q], d = pw[q];
        r[q * 4 + 0] = a.x + bb.x + (x1.x - x0.x) * invw + d.x;
        r[q * 4 + 1] = a.y + bb.y + (x1.y - x0.y) * invw + d.y;
        r[q * 4 + 2] = a.z + bb.z + (x1.z - x0.z) * invw + d.z;
        r[q * 4 + 3] = a.w + bb.w + (x1.w - x0.w) * invw + d.w;
    }

    #pragma unroll
    for (int l = 0; l < NUM_LABELS; l++)
        so[threadIdx.x * NUM_LABELS + l] = r[l];
    __syncthreads();

    float4* ob = (float4*)(out + (size_t)blockIdx.x * SPAN_BLK * NUM_LABELS);
    const float4* sb = (const float4*)so;
    #pragma unroll
    for (int i = threadIdx.x; i < SPAN_BLK * NUM_LABELS / 4; i += SPAN_BLK)
        ob[i] = sb[i];
}

// ---------------------------------------------------------------------------
// Launcher
// ---------------------------------------------------------------------------
extern "C" void kernel_launch(void* const* d_in, const int* in_sizes, int n_in,
                              void* d_out, int out_size) {
    const float* seq   = (const float*)d_in[0];   // [1, 512, 768]
    const int*   sidx  = (const int*)d_in[1];     // [32768]
    const int*   eidx  = (const int*)d_in[2];     // [32768]
    const int*   widx  = (const int*)d_in[3];     // [32768]
    const float* wtab  = (const float*)d_in[4];   // [17, 50]
    const float* W     = (const float*)d_in[5];   // [9, 2354]
    const float* b     = (const float*)d_in[6];   // [9]
    float* out = (float*)d_out;                   // [32768, 9]

    proj_kernel<<<PROJ_GRID, PROJ_TPB>>>(seq, W);
    scan_kernel<<<1, 288>>>(wtab, W, b);
    span_kernel<<<N_SPANS / SPAN_BLK, SPAN_BLK>>>(sidx, eidx, widx, out);
}